// round 2
// baseline (speedup 1.0000x reference)
#include <cuda_runtime.h>
#include <cuda_bf16.h>
#include <math.h>

#define NN 50000
#define EE 800000
#define DD 96
#define KTOT 288            // 3 * DD
#define BN_EPS 1e-5f

// ---------------- scratch (static device globals; no allocation) ----------------
__device__ float  g_T1[NN * DD];
__device__ float  g_T2[NN * DD];
__device__ int    g_degi[NN];
__device__ float  g_dis[NN];
__device__ int    g_count[NN];
__device__ int    g_colptr[NN + 1];
__device__ int    g_cursor[NN];
__device__ int    g_esrc[EE];
__device__ float  g_ew[EE];
__device__ double g_sum[DD];
__device__ double g_sumsq[DD];
__device__ float  g_scale[DD];
__device__ float  g_shift[DD];

// ---------------- setup kernels ----------------

__global__ void zero_kernel() {
    int i = blockIdx.x * blockDim.x + threadIdx.x;
    int stride = gridDim.x * blockDim.x;
    for (int k = i; k < NN; k += stride) { g_degi[k] = 0; g_count[k] = 0; }
    if (i < DD) { g_sum[i] = 0.0; g_sumsq[i] = 0.0; }
}

__global__ void count_kernel(const int* __restrict__ ei) {
    int e = blockIdx.x * blockDim.x + threadIdx.x;
    if (e >= EE) return;
    int r = ei[e];
    int c = ei[EE + e];
    if (r != c) atomicAdd(&g_degi[r], 1);
    atomicAdd(&g_count[c], 1);
}

__global__ void dis_kernel() {
    int n = blockIdx.x * blockDim.x + threadIdx.x;
    if (n >= NN) return;
    int d = g_degi[n];
    g_dis[n] = (d > 0) ? rsqrtf((float)d) : 0.0f;
}

// exclusive scan of g_count -> g_colptr/g_cursor. 1 block, 1024 threads,
// 4 elements/thread/iter, shfl-based warp scans (4 barriers per iter).
__global__ void scan_kernel() {
    __shared__ int warpsum[32];
    __shared__ int s_carry;
    int tid = threadIdx.x;
    int lane = tid & 31, wid = tid >> 5;
    if (tid == 0) s_carry = 0;
    __syncthreads();
    for (int base = 0; base < NN; base += 4096) {
        int carry = s_carry;
        int i0 = base + tid * 4;
        int v0 = (i0 + 0 < NN) ? g_count[i0 + 0] : 0;
        int v1 = (i0 + 1 < NN) ? g_count[i0 + 1] : 0;
        int v2 = (i0 + 2 < NN) ? g_count[i0 + 2] : 0;
        int v3 = (i0 + 3 < NN) ? g_count[i0 + 3] : 0;
        int tsum = v0 + v1 + v2 + v3;
        // inclusive warp scan of tsum
        int xs = tsum;
        #pragma unroll
        for (int off = 1; off < 32; off <<= 1) {
            int y = __shfl_up_sync(0xffffffffu, xs, off);
            if (lane >= off) xs += y;
        }
        if (lane == 31) warpsum[wid] = xs;
        __syncthreads();
        if (wid == 0) {
            int w = warpsum[lane];
            #pragma unroll
            for (int off = 1; off < 32; off <<= 1) {
                int y = __shfl_up_sync(0xffffffffu, w, off);
                if (lane >= off) w += y;
            }
            warpsum[lane] = w;
        }
        __syncthreads();
        int wprefix = (wid > 0) ? warpsum[wid - 1] : 0;
        int total = warpsum[31];
        int run = carry + wprefix + (xs - tsum);
        if (i0 + 0 < NN) { g_colptr[i0 + 0] = run; g_cursor[i0 + 0] = run; } run += v0;
        if (i0 + 1 < NN) { g_colptr[i0 + 1] = run; g_cursor[i0 + 1] = run; } run += v1;
        if (i0 + 2 < NN) { g_colptr[i0 + 2] = run; g_cursor[i0 + 2] = run; } run += v2;
        if (i0 + 3 < NN) { g_colptr[i0 + 3] = run; g_cursor[i0 + 3] = run; } run += v3;
        __syncthreads();
        if (tid == 0) s_carry = carry + total;
        __syncthreads();
    }
    if (threadIdx.x == 0) g_colptr[NN] = EE;
}

__global__ void fill_kernel(const int* __restrict__ ei) {
    int e = blockIdx.x * blockDim.x + threadIdx.x;
    if (e >= EE) return;
    int r = ei[e];
    int c = ei[EE + e];
    float w = (r != c) ? (-g_dis[r] * g_dis[c]) : 0.0f;
    int pos = atomicAdd(&g_cursor[c], 1);
    g_esrc[pos] = r;
    g_ew[pos]   = w;
}

// ---------------- propagation: warp-per-node, shfl-broadcast edges ----------------
// MODE 0: g_T1 = L_hat @ x
// MODE 1: g_T2 = 2 * (L_hat @ g_T1) - x
template <int MODE>
__global__ void prop_kernel(const float* __restrict__ x) {
    const int WPB = 16;                        // warps per block (512 threads)
    int wid = threadIdx.x >> 5;
    int lane = threadIdx.x & 31;
    int node = blockIdx.x * WPB + wid;
    if (node >= NN) return;
    const float* __restrict__ src = (MODE == 0) ? x : g_T1;
    int s = g_colptr[node];
    int e = g_colptr[node + 1];
    float a0 = 0.0f, a1 = 0.0f, a2 = 0.0f;
    for (int base = s; base < e; base += 32) {
        int idx = base + lane;
        int   sv = 0;
        float wv = 0.0f;
        if (idx < e) { sv = g_esrc[idx]; wv = g_ew[idx]; }
        int cnt = min(32, e - base);
        for (int j = 0; j < cnt; j++) {
            int   sj = __shfl_sync(0xffffffffu, sv, j);
            float wj = __shfl_sync(0xffffffffu, wv, j);
            const float* __restrict__ p = src + sj * DD;
            a0 += wj * p[lane];
            a1 += wj * p[lane + 32];
            a2 += wj * p[lane + 64];
        }
    }
    int o = node * DD;
    if (MODE == 0) {
        g_T1[o + lane]      = a0;
        g_T1[o + lane + 32] = a1;
        g_T1[o + lane + 64] = a2;
    } else {
        g_T2[o + lane]      = 2.0f * a0 - x[o + lane];
        g_T2[o + lane + 32] = 2.0f * a1 - x[o + lane + 32];
        g_T2[o + lane + 64] = 2.0f * a2 - x[o + lane + 64];
    }
}

// ---------------- fused GEMM + bias + BN partial stats ----------------
// out[n,:] = [x | T1 | T2][n,:] @ [W0;W1;W2] + bias
// Register-blocked: 96 threads, thread = (grp = tid/48, jj = tid%48),
// computes cols {jj, jj+48} for 8 rows of its group; 16 rows per iter,
// 64 rows per block.
#define GEMM_RPG 8                  // rows per group per iter
#define GEMM_RPI 16                 // rows per iter (2 groups)
#define GEMM_ROWS 64                // rows per block
#define SH_PITCH 9                  // row pad within k (8 rows -> 9)
#define SH_GRP   (KTOT * SH_PITCH + 1)   // +1 float: degrp banks by 1

__global__ void gemm_kernel(const float* __restrict__ x,
                            const float* __restrict__ W,
                            const float* __restrict__ bias,
                            float* __restrict__ out) {
    __shared__ float sh[2 * SH_GRP];
    int tid = threadIdx.x;
    int grp = tid / 48;             // 0 or 1
    int jj  = tid % 48;             // column pair base
    int row0 = blockIdx.x * GEMM_ROWS;
    float b0 = bias[jj];
    float b1 = bias[jj + 48];
    double s0 = 0.0, s1 = 0.0, q0 = 0.0, q1 = 0.0;

    for (int it = 0; it < GEMM_ROWS / GEMM_RPI; it++) {
        int rbase = row0 + it * GEMM_RPI;
        // cooperative load of 16 rows x 288 cols into shared
        for (int idx = tid; idx < GEMM_RPI * KTOT; idx += 96) {
            int r16 = idx / KTOT;           // 0..15
            int k   = idx - r16 * KTOT;     // 0..287
            int n   = rbase + r16;
            float v = 0.0f;
            if (n < NN) {
                if (k < DD)            v = x[n * DD + k];
                else if (k < 2 * DD)   v = g_T1[n * DD + (k - DD)];
                else                   v = g_T2[n * DD + (k - 2 * DD)];
            }
            int g = r16 >> 3;               // group
            int r = r16 & 7;
            sh[g * SH_GRP + k * SH_PITCH + r] = v;
        }
        __syncthreads();

        float acc0[GEMM_RPG], acc1[GEMM_RPG];
        #pragma unroll
        for (int r = 0; r < GEMM_RPG; r++) { acc0[r] = 0.0f; acc1[r] = 0.0f; }

        const float* shg = &sh[grp * SH_GRP];
        #pragma unroll 4
        for (int k = 0; k < KTOT; k++) {
            float w0 = W[k * DD + jj];
            float w1 = W[k * DD + jj + 48];
            #pragma unroll
            for (int r = 0; r < GEMM_RPG; r++) {
                float in = shg[k * SH_PITCH + r];
                acc0[r] += in * w0;
                acc1[r] += in * w1;
            }
        }

        #pragma unroll
        for (int r = 0; r < GEMM_RPG; r++) {
            int n = rbase + grp * GEMM_RPG + r;
            if (n < NN) {
                float o0 = acc0[r] + b0;
                float o1 = acc1[r] + b1;
                out[n * DD + jj]      = o0;
                out[n * DD + jj + 48] = o1;
                s0 += (double)o0; q0 += (double)o0 * (double)o0;
                s1 += (double)o1; q1 += (double)o1 * (double)o1;
            }
        }
        __syncthreads();
    }
    atomicAdd(&g_sum[jj], s0);
    atomicAdd(&g_sumsq[jj], q0);
    atomicAdd(&g_sum[jj + 48], s1);
    atomicAdd(&g_sumsq[jj + 48], q1);
}

// ---------------- batch-norm ----------------
__global__ void bnparam_kernel(const float* __restrict__ gamma,
                               const float* __restrict__ beta) {
    int j = threadIdx.x;
    if (j >= DD) return;
    double mean = g_sum[j] / (double)NN;
    double var  = g_sumsq[j] / (double)NN - mean * mean;
    float inv = rsqrtf((float)var + BN_EPS);
    float sc = inv * gamma[j];
    g_scale[j] = sc;
    g_shift[j] = beta[j] - (float)mean * sc;
}

__global__ void bnapply_kernel(float* __restrict__ out) {
    // out is NN*DD floats = 1.2M float4; feature index = (elem idx) % 96.
    int i = blockIdx.x * blockDim.x + threadIdx.x;
    int stride = gridDim.x * blockDim.x;
    float4* o4 = (float4*)out;
    const int total4 = NN * DD / 4;
    for (int t = i; t < total4; t += stride) {
        int f = (t * 4) % DD;       // 96 % 4 == 0, so f..f+3 stay in range
        float4 v = o4[t];
        v.x = v.x * g_scale[f]     + g_shift[f];
        v.y = v.y * g_scale[f + 1] + g_shift[f + 1];
        v.z = v.z * g_scale[f + 2] + g_shift[f + 2];
        v.w = v.w * g_scale[f + 3] + g_shift[f + 3];
        o4[t] = v;
    }
}

// ---------------- launch ----------------
extern "C" void kernel_launch(void* const* d_in, const int* in_sizes, int n_in,
                              void* d_out, int out_size) {
    const float* x     = (const float*)d_in[0];
    const int*   ei    = (const int*)d_in[1];
    const float* W     = (const float*)d_in[2];
    const float* bias  = (const float*)d_in[3];
    const float* gamma = (const float*)d_in[4];
    const float* beta  = (const float*)d_in[5];
    float* out = (float*)d_out;

    zero_kernel<<<256, 256>>>();
    count_kernel<<<(EE + 255) / 256, 256>>>(ei);
    dis_kernel<<<(NN + 255) / 256, 256>>>();
    scan_kernel<<<1, 1024>>>();
    fill_kernel<<<(EE + 255) / 256, 256>>>(ei);
    prop_kernel<0><<<(NN + 15) / 16, 512>>>(x);   // T1 = L_hat @ x
    prop_kernel<1><<<(NN + 15) / 16, 512>>>(x);   // T2 = 2*L_hat@T1 - x
    gemm_kernel<<<(NN + GEMM_ROWS - 1) / GEMM_ROWS, 96>>>(x, W, bias, out);
    bnparam_kernel<<<1, DD>>>(gamma, beta);
    bnapply_kernel<<<1024, 256>>>(out);
}

// round 11
// speedup vs baseline: 1.2613x; 1.2613x over previous
#include <cuda_runtime.h>
#include <cuda_bf16.h>
#include <math.h>

#define NN 50000
#define EE 800000
#define DD 96
#define KTOT 288            // 3 * DD
#define BN_EPS 1e-5f

#define SCAN_CHUNK 4096
#define SCAN_NB ((NN + SCAN_CHUNK - 1) / SCAN_CHUNK)   // 13

// ---------------- scratch (static device globals; no allocation) ----------------
__device__ float  g_T1[NN * DD];
__device__ float  g_T2[NN * DD];
__device__ int    g_degi[NN];
__device__ float  g_dis[NN];
__device__ int    g_count[NN];
__device__ int    g_colptr[NN + 1];
__device__ int    g_cursor[NN];
__device__ int2   g_epack[EE];      // {src, __float_as_int(w)}
__device__ int    g_bsum[SCAN_NB];
__device__ double g_sum[DD];
__device__ double g_sumsq[DD];

// ---------------- f32x2 helpers (sm_103a packed fp32 FMA) ----------------
__device__ __forceinline__ unsigned long long splat2(float a) {
    unsigned long long r;
    unsigned int u = __float_as_uint(a);
    asm("mov.b64 %0, {%1, %1};" : "=l"(r) : "r"(u));
    return r;
}
__device__ __forceinline__ void fma2(unsigned long long& acc,
                                     unsigned long long a,
                                     unsigned long long b) {
    asm("fma.rn.f32x2 %0, %1, %2, %0;" : "+l"(acc) : "l"(a), "l"(b));
}
__device__ __forceinline__ void unpack2(unsigned long long v, float& lo, float& hi) {
    asm("mov.b64 {%0, %1}, %2;" : "=f"(lo), "=f"(hi) : "l"(v));
}

// ---------------- setup kernels ----------------

__global__ void zero_kernel() {
    int i = blockIdx.x * blockDim.x + threadIdx.x;
    int stride = gridDim.x * blockDim.x;
    for (int k = i; k < NN; k += stride) { g_degi[k] = 0; g_count[k] = 0; }
    if (i < DD) { g_sum[i] = 0.0; g_sumsq[i] = 0.0; }
}

__global__ void count_kernel(const int* __restrict__ ei) {
    int e = blockIdx.x * blockDim.x + threadIdx.x;
    if (e >= EE) return;
    int r = ei[e];
    int c = ei[EE + e];
    if (r != c) atomicAdd(&g_degi[r], 1);
    atomicAdd(&g_count[c], 1);
}

// ---- 2-phase parallel exclusive scan of g_count -> g_colptr/g_cursor.
// Phase 1 also computes g_dis (both depend only on count_kernel).

__global__ void scan_local_kernel() {
    __shared__ int warpsum[32];
    int tid = threadIdx.x;
    int lane = tid & 31, wid = tid >> 5;
    int i0 = blockIdx.x * SCAN_CHUNK + tid * 4;
    int v0 = (i0 + 0 < NN) ? g_count[i0 + 0] : 0;
    int v1 = (i0 + 1 < NN) ? g_count[i0 + 1] : 0;
    int v2 = (i0 + 2 < NN) ? g_count[i0 + 2] : 0;
    int v3 = (i0 + 3 < NN) ? g_count[i0 + 3] : 0;

    // fused: g_dis for the same 4 nodes (independent of scan result)
    #pragma unroll
    for (int q = 0; q < 4; q++) {
        int i = i0 + q;
        if (i < NN) {
            int d = g_degi[i];
            g_dis[i] = (d > 0) ? rsqrtf((float)d) : 0.0f;
        }
    }

    int tsum = v0 + v1 + v2 + v3;
    int xs = tsum;
    #pragma unroll
    for (int off = 1; off < 32; off <<= 1) {
        int y = __shfl_up_sync(0xffffffffu, xs, off);
        if (lane >= off) xs += y;
    }
    if (lane == 31) warpsum[wid] = xs;
    __syncthreads();
    if (wid == 0) {
        int w = warpsum[lane];
        #pragma unroll
        for (int off = 1; off < 32; off <<= 1) {
            int y = __shfl_up_sync(0xffffffffu, w, off);
            if (lane >= off) w += y;
        }
        warpsum[lane] = w;
    }
    __syncthreads();
    int wprefix = (wid > 0) ? warpsum[wid - 1] : 0;
    int run = wprefix + (xs - tsum);           // local exclusive prefix
    if (i0 + 0 < NN) g_colptr[i0 + 0] = run; run += v0;
    if (i0 + 1 < NN) g_colptr[i0 + 1] = run; run += v1;
    if (i0 + 2 < NN) g_colptr[i0 + 2] = run; run += v2;
    if (i0 + 3 < NN) g_colptr[i0 + 3] = run; run += v3;
    if (tid == 1023) g_bsum[blockIdx.x] = warpsum[31];
}

// Phase 2: each block redundantly scans the 13 block sums in one warp,
// then adds its own block's base. (Removes the separate bsum kernel.)
__global__ void scan_add_kernel() {
    __shared__ int s_base;
    int tid = threadIdx.x;
    if (tid < 32) {
        int v = (tid < SCAN_NB) ? g_bsum[tid] : 0;
        int xs = v;
        #pragma unroll
        for (int off = 1; off < 32; off <<= 1) {
            int y = __shfl_up_sync(0xffffffffu, xs, off);
            if (tid >= off) xs += y;
        }
        if (tid == blockIdx.x) s_base = xs - v;   // exclusive prefix for this block
    }
    __syncthreads();
    int base = s_base;
    int i0 = blockIdx.x * SCAN_CHUNK + tid * 4;
    #pragma unroll
    for (int q = 0; q < 4; q++) {
        int i = i0 + q;
        if (i < NN) {
            int v = g_colptr[i] + base;
            g_colptr[i] = v;
            g_cursor[i] = v;
        }
    }
    if (blockIdx.x == 0 && tid == 0) g_colptr[NN] = EE;
}

__global__ void fill_kernel(const int* __restrict__ ei) {
    int e = blockIdx.x * blockDim.x + threadIdx.x;
    if (e >= EE) return;
    int r = ei[e];
    int c = ei[EE + e];
    float w = (r != c) ? (-g_dis[r] * g_dis[c]) : 0.0f;
    int pos = atomicAdd(&g_cursor[c], 1);
    g_epack[pos] = make_int2(r, __float_as_int(w));
}

// ---------------- propagation: warp-per-node, float4 gathers ----------------
// Lanes 0..23 each own features 4*lane .. 4*lane+3 (96 = 24 * 4).
// MODE 0: g_T1 = L_hat @ x
// MODE 1: g_T2 = 2 * (L_hat @ g_T1) - x
template <int MODE>
__global__ void prop_kernel(const float* __restrict__ x) {
    const int WPB = 16;                        // warps per block (512 threads)
    int wid = threadIdx.x >> 5;
    int lane = threadIdx.x & 31;
    int node = blockIdx.x * WPB + wid;
    if (node >= NN) return;
    const float* __restrict__ src = (MODE == 0) ? x : g_T1;
    int s = g_colptr[node];
    int e = g_colptr[node + 1];
    float4 acc = make_float4(0.f, 0.f, 0.f, 0.f);
    float4 acd = make_float4(0.f, 0.f, 0.f, 0.f);
    bool active = (lane < 24);
    for (int base = s; base < e; base += 32) {
        int idx = base + lane;
        int   sv = 0;
        float wv = 0.0f;
        if (idx < e) {
            int2 p = g_epack[idx];
            sv = p.x;
            wv = __int_as_float(p.y);
        }
        int cnt = min(32, e - base);
        int j = 0;
        // 2-way unrolled broadcast loop: 2 independent gathers in flight
        for (; j + 2 <= cnt; j += 2) {
            int   sj0 = __shfl_sync(0xffffffffu, sv, j);
            float wj0 = __shfl_sync(0xffffffffu, wv, j);
            int   sj1 = __shfl_sync(0xffffffffu, sv, j + 1);
            float wj1 = __shfl_sync(0xffffffffu, wv, j + 1);
            if (active) {
                float4 v0 = *(const float4*)(src + sj0 * DD + 4 * lane);
                float4 v1 = *(const float4*)(src + sj1 * DD + 4 * lane);
                acc.x += wj0 * v0.x; acc.y += wj0 * v0.y;
                acc.z += wj0 * v0.z; acc.w += wj0 * v0.w;
                acd.x += wj1 * v1.x; acd.y += wj1 * v1.y;
                acd.z += wj1 * v1.z; acd.w += wj1 * v1.w;
            }
        }
        if (j < cnt) {
            int   sj = __shfl_sync(0xffffffffu, sv, j);
            float wj = __shfl_sync(0xffffffffu, wv, j);
            if (active) {
                float4 v = *(const float4*)(src + sj * DD + 4 * lane);
                acc.x += wj * v.x; acc.y += wj * v.y;
                acc.z += wj * v.z; acc.w += wj * v.w;
            }
        }
    }
    if (active) {
        acc.x += acd.x; acc.y += acd.y; acc.z += acd.z; acc.w += acd.w;
        int o = node * DD + 4 * lane;
        if (MODE == 0) {
            *(float4*)(g_T1 + o) = acc;
        } else {
            float4 xv = *(const float4*)(x + o);
            float4 r;
            r.x = 2.0f * acc.x - xv.x;
            r.y = 2.0f * acc.y - xv.y;
            r.z = 2.0f * acc.z - xv.z;
            r.w = 2.0f * acc.w - xv.w;
            *(float4*)(g_T2 + o) = r;
        }
    }
}

// ---------------- fused GEMM + bias + BN partial stats (f32x2) ----------------
// 192 threads = 2 independent halves of 96 threads; each half processes 64 rows
// (4 iters x 16 rows). Within a half: grp = t96/48 picks an 8-row group,
// jj = 2*(t96%48) picks an adjacent column pair. Row pairs are packed into
// 64-bit f32x2 accumulators; tile rows are read via broadcast LDS.64.
#define GEMM_RPI 16                 // rows per iter per half
#define GEMM_ROWS 64                // rows per half
#define SH_PITCH 10                 // 8 rows padded to 10 (keeps 8B alignment)
#define SH_GRP   (KTOT * SH_PITCH)  // floats per 8-row group (2880, 8B-multiple)

__global__ void __launch_bounds__(192) gemm_kernel(const float* __restrict__ x,
                                                   const float* __restrict__ W,
                                                   const float* __restrict__ bias,
                                                   float* __restrict__ out) {
    __shared__ __align__(16) float sh[4 * SH_GRP];
    int tid  = threadIdx.x;
    int half = tid / 96;            // 0 or 1
    int t96  = tid - half * 96;
    int grp  = t96 / 48;            // 0 or 1
    int jj   = 2 * (t96 % 48);      // adjacent column pair {jj, jj+1}
    int row0 = (blockIdx.x * 2 + half) * GEMM_ROWS;
    float2 bv = *(const float2*)(bias + jj);
    double s0 = 0.0, s1 = 0.0, q0 = 0.0, q1 = 0.0;
    float* shh = &sh[half * 2 * SH_GRP];

    for (int it = 0; it < GEMM_ROWS / GEMM_RPI; it++) {
        int rbase = row0 + it * GEMM_RPI;
        // cooperative load of 16 rows x 288 cols into this half's shared area
        for (int idx = t96; idx < GEMM_RPI * KTOT; idx += 96) {
            int r16 = idx / KTOT;           // 0..15
            int k   = idx - r16 * KTOT;     // 0..287
            int n   = rbase + r16;
            float v = 0.0f;
            if (n < NN) {
                if (k < DD)            v = x[n * DD + k];
                else if (k < 2 * DD)   v = g_T1[n * DD + (k - DD)];
                else                   v = g_T2[n * DD + (k - 2 * DD)];
            }
            int g = r16 >> 3;
            int r = r16 & 7;
            shh[g * SH_GRP + k * SH_PITCH + r] = v;
        }
        __syncthreads();

        // acc0[rp]: col jj,   rows {2rp, 2rp+1};  acc1[rp]: col jj+1
        unsigned long long acc0[4] = {0ull, 0ull, 0ull, 0ull};
        unsigned long long acc1[4] = {0ull, 0ull, 0ull, 0ull};

        const unsigned long long* shg64 =
            (const unsigned long long*)(shh + grp * SH_GRP);
        #pragma unroll 4
        for (int k = 0; k < KTOT; k++) {
            float2 wv = *(const float2*)(W + k * DD + jj);   // LDG.64
            unsigned long long w0 = splat2(wv.x);
            unsigned long long w1 = splat2(wv.y);
            int kb = k * (SH_PITCH / 2);                      // 64-bit index
            unsigned long long p0 = shg64[kb + 0];            // rows 0,1 (broadcast)
            unsigned long long p1 = shg64[kb + 1];            // rows 2,3
            unsigned long long p2 = shg64[kb + 2];            // rows 4,5
            unsigned long long p3 = shg64[kb + 3];            // rows 6,7
            fma2(acc0[0], p0, w0); fma2(acc1[0], p0, w1);
            fma2(acc0[1], p1, w0); fma2(acc1[1], p1, w1);
            fma2(acc0[2], p2, w0); fma2(acc1[2], p2, w1);
            fma2(acc0[3], p3, w0); fma2(acc1[3], p3, w1);
        }

        #pragma unroll
        for (int rp = 0; rp < 4; rp++) {
            float a_lo, a_hi, b_lo, b_hi;
            unpack2(acc0[rp], a_lo, a_hi);
            unpack2(acc1[rp], b_lo, b_hi);
            int n0 = rbase + grp * 8 + 2 * rp;
            if (n0 < NN) {
                float o0 = a_lo + bv.x, o1 = b_lo + bv.y;
                *(float2*)(out + n0 * DD + jj) = make_float2(o0, o1);
                s0 += (double)o0; q0 += (double)o0 * (double)o0;
                s1 += (double)o1; q1 += (double)o1 * (double)o1;
            }
            if (n0 + 1 < NN) {
                float o0 = a_hi + bv.x, o1 = b_hi + bv.y;
                *(float2*)(out + (n0 + 1) * DD + jj) = make_float2(o0, o1);
                s0 += (double)o0; q0 += (double)o0 * (double)o0;
                s1 += (double)o1; q1 += (double)o1 * (double)o1;
            }
        }
        __syncthreads();
    }
    atomicAdd(&g_sum[jj], s0);
    atomicAdd(&g_sumsq[jj], q0);
    atomicAdd(&g_sum[jj + 1], s1);
    atomicAdd(&g_sumsq[jj + 1], q1);
}

// ---------------- batch-norm apply (computes scale/shift per block) ----------------
__global__ void bnapply_kernel(const float* __restrict__ gamma,
                               const float* __restrict__ beta,
                               float* __restrict__ out) {
    __shared__ float s_scale[DD];
    __shared__ float s_shift[DD];
    int tid = threadIdx.x;
    if (tid < DD) {
        double mean = g_sum[tid] / (double)NN;
        double var  = g_sumsq[tid] / (double)NN - mean * mean;
        float inv = rsqrtf((float)var + BN_EPS);
        float sc = inv * gamma[tid];
        s_scale[tid] = sc;
        s_shift[tid] = beta[tid] - (float)mean * sc;
    }
    __syncthreads();
    int i = blockIdx.x * blockDim.x + tid;
    int stride = gridDim.x * blockDim.x;
    float4* o4 = (float4*)out;
    const int total4 = NN * DD / 4;
    for (int t = i; t < total4; t += stride) {
        int f = (t * 4) % DD;       // 96 % 4 == 0, so f..f+3 stay in range
        float4 v = o4[t];
        v.x = v.x * s_scale[f]     + s_shift[f];
        v.y = v.y * s_scale[f + 1] + s_shift[f + 1];
        v.z = v.z * s_scale[f + 2] + s_shift[f + 2];
        v.w = v.w * s_scale[f + 3] + s_shift[f + 3];
        o4[t] = v;
    }
}

// ---------------- launch ----------------
extern "C" void kernel_launch(void* const* d_in, const int* in_sizes, int n_in,
                              void* d_out, int out_size) {
    const float* x     = (const float*)d_in[0];
    const int*   ei    = (const int*)d_in[1];
    const float* W     = (const float*)d_in[2];
    const float* bias  = (const float*)d_in[3];
    const float* gamma = (const float*)d_in[4];
    const float* beta  = (const float*)d_in[5];
    float* out = (float*)d_out;

    zero_kernel<<<256, 256>>>();
    count_kernel<<<(EE + 255) / 256, 256>>>(ei);
    scan_local_kernel<<<SCAN_NB, 1024>>>();   // also computes g_dis
    scan_add_kernel<<<SCAN_NB, 1024>>>();     // folds in the 13-element bsum scan
    fill_kernel<<<(EE + 255) / 256, 256>>>(ei);
    prop_kernel<0><<<(NN + 15) / 16, 512>>>(x);   // T1 = L_hat @ x
    prop_kernel<1><<<(NN + 15) / 16, 512>>>(x);   // T2 = 2*L_hat@T1 - x
    gemm_kernel<<<(NN + 127) / 128, 192>>>(x, W, bias, out);
    bnapply_kernel<<<512, 256>>>(gamma, beta, out);  // folds in BN param calc
}